// round 1
// baseline (speedup 1.0000x reference)
#include <cuda_runtime.h>
#include <math.h>

#define D_H   128
#define D_E   64
#define F0    320   // 2*D_H + D_E
#define H1    256
#define H2    128
#define MAX_NODES 50000
#define MAX_EDGES 800000

// ---------------- device scratch (allocation-free rule: __device__ globals) ---------
__device__ float g_y1[(size_t)MAX_EDGES * H1];   // 819 MB
__device__ float g_y2[(size_t)MAX_EDGES * H2];   // 410 MB
__device__ int   g_cnt_src[MAX_NODES];
__device__ int   g_cnt_dst[MAX_NODES];
__device__ float g_sum0[F0], g_sq0[F0];
__device__ float g_sum1[H1], g_sq1[H1];
__device__ float g_sum2[H2], g_sq2[H2];
__device__ float g_scale0[F0], g_shift0[F0];
__device__ float g_scale1[H1], g_shift1[H1];
__device__ float g_scale2[H2], g_shift2[H2];
__device__ float g_W1t[F0 * H1], g_b1f[H1];      // BN0-folded, transposed [K][N]
__device__ float g_W2t[H1 * H2], g_b2f[H2];
__device__ float g_W3f[H2];
__device__ float g_b3f[1];

// ---------------- tiny setup kernels -----------------------------------------------
__global__ void zero_kernel(int n_nodes) {
    int i = blockIdx.x * blockDim.x + threadIdx.x;
    if (i < n_nodes) { g_cnt_src[i] = 0; g_cnt_dst[i] = 0; }
    if (i < F0) { g_sum0[i] = 0.f; g_sq0[i] = 0.f; }
    if (i < H1) { g_sum1[i] = 0.f; g_sq1[i] = 0.f; }
    if (i < H2) { g_sum2[i] = 0.f; g_sq2[i] = 0.f; }
}

__global__ void count_kernel(const int* __restrict__ src, const int* __restrict__ dst,
                             int n_edges) {
    int i = blockIdx.x * blockDim.x + threadIdx.x;
    if (i < n_edges) {
        atomicAdd(&g_cnt_src[src[i]], 1);
        atomicAdd(&g_cnt_dst[dst[i]], 1);
    }
}

// BN0 stats for the h[src] / h[dst] parts via degree-weighted node reduce.
#define NPB 256
__global__ void hstats_kernel(const float* __restrict__ h, int n_nodes) {
    __shared__ float c1s[NPB], c2s[NPB];
    int t  = threadIdx.x;               // 128 threads = feature id
    int v0 = blockIdx.x * NPB;
    for (int i = t; i < NPB; i += 128) {
        int v = v0 + i;
        c1s[i] = (v < n_nodes) ? (float)g_cnt_src[v] : 0.f;
        c2s[i] = (v < n_nodes) ? (float)g_cnt_dst[v] : 0.f;
    }
    __syncthreads();
    float s1 = 0.f, q1 = 0.f, s2 = 0.f, q2 = 0.f;
    int lim = n_nodes - v0; if (lim > NPB) lim = NPB;
    for (int i = 0; i < lim; i++) {
        float x  = h[(long)(v0 + i) * D_H + t];
        float x2 = x * x;
        s1 += c1s[i] * x; q1 += c1s[i] * x2;
        s2 += c2s[i] * x; q2 += c2s[i] * x2;
    }
    atomicAdd(&g_sum0[t], s1);          atomicAdd(&g_sq0[t], q1);
    atomicAdd(&g_sum0[D_H + t], s2);    atomicAdd(&g_sq0[D_H + t], q2);
}

// BN0 stats for the e part: plain column reduce.
__global__ void estats_kernel(const float* __restrict__ e, int n_edges) {
    int t = threadIdx.x & 63;
    int r = threadIdx.x >> 6;
    float s = 0.f, q = 0.f;
    for (long row = (long)blockIdx.x * 4 + r; row < n_edges; row += (long)gridDim.x * 4) {
        float x = e[row * D_E + t];
        s += x; q += x * x;
    }
    atomicAdd(&g_sum0[2 * D_H + t], s);
    atomicAdd(&g_sq0 [2 * D_H + t], q);
}

// column stats of an M x N activation matrix (blockDim.x == N)
__global__ void colstats_kernel(const float* __restrict__ X, float* __restrict__ sum,
                                float* __restrict__ sq, int M, int N) {
    int t = threadIdx.x;
    float s = 0.f, q = 0.f;
    for (long r = blockIdx.x; r < M; r += gridDim.x) {
        float x = X[r * N + t];
        s += x; q += x * x;
    }
    atomicAdd(&sum[t], s);
    atomicAdd(&sq[t], q);
}

// scale/shift from raw sums (biased variance, eps = 1e-5)
__global__ void affine_kernel(const float* __restrict__ sum, const float* __restrict__ sq,
                              const float* __restrict__ g, const float* __restrict__ b,
                              float* __restrict__ scale, float* __restrict__ shift,
                              int K, float invM) {
    int j = blockIdx.x * blockDim.x + threadIdx.x;
    if (j < K) {
        float mean = sum[j] * invM;
        float var  = sq[j] * invM - mean * mean;
        float sc   = g[j] * rsqrtf(var + 1e-5f);
        scale[j] = sc;
        shift[j] = b[j] - mean * sc;
    }
}

// Wt[j][o] = W[o][j] * scale[j]   (W is [N][K] row-major, Wt is [K][N])
__global__ void foldT_kernel(const float* __restrict__ W, const float* __restrict__ scale,
                             float* __restrict__ Wt, int N, int K) {
    int idx = blockIdx.x * blockDim.x + threadIdx.x;
    if (idx < N * K) {
        int j = idx / N, o = idx % N;
        Wt[idx] = W[(long)o * K + j] * scale[j];
    }
}

// bout[o] = b[o] + sum_j W[o][j] * shift[j]   (one block per o, 128 threads)
__global__ void foldB_kernel(const float* __restrict__ W, const float* __restrict__ bvec,
                             const float* __restrict__ shift, float* __restrict__ bout,
                             int K) {
    int o = blockIdx.x, t = threadIdx.x;
    float s = 0.f;
    for (int j = t; j < K; j += 128) s += W[(long)o * K + j] * shift[j];
    __shared__ float red[128];
    red[t] = s; __syncthreads();
    for (int w = 64; w > 0; w >>= 1) { if (t < w) red[t] += red[t + w]; __syncthreads(); }
    if (t == 0) bout[o] = bvec[o] + red[0];
}

// fold BN2 into W3 (H2 == 128, single block)
__global__ void fold3_kernel(const float* __restrict__ W3, const float* __restrict__ b3) {
    int t = threadIdx.x;
    float w = W3[t];
    g_W3f[t] = w * g_scale2[t];
    __shared__ float red[128];
    red[t] = w * g_shift2[t]; __syncthreads();
    for (int w2 = 64; w2 > 0; w2 >>= 1) { if (t < w2) red[t] += red[t + w2]; __syncthreads(); }
    if (t == 0) g_b3f[0] = b3[0] + red[0];
}

// final layer: out[i] = y2[i,:] . W3f + b3f  (one warp per row)
__global__ void out_kernel(const float* __restrict__ Y2, float* __restrict__ out, int M) {
    int warp = (blockIdx.x * blockDim.x + threadIdx.x) >> 5;
    int lane = threadIdx.x & 31;
    if (warp >= M) return;
    const float* row = Y2 + (long)warp * H2;
    float s = row[lane]      * g_W3f[lane]
            + row[lane + 32] * g_W3f[lane + 32]
            + row[lane + 64] * g_W3f[lane + 64]
            + row[lane + 96] * g_W3f[lane + 96];
    #pragma unroll
    for (int o = 16; o > 0; o >>= 1) s += __shfl_down_sync(0xffffffffu, s, o);
    if (lane == 0) out[warp] = s + g_b3f[0];
}

// ---------------- main GEMMs: 128x128x8 tiles, 8x8 per thread, fp32 ----------------
// Y[m][n] = relu( sum_k A[m][k] * Bt[k][n] + bias[n] )
// GATHER=true: A row m = concat(h[src[m]], h[dst[m]], e[m])

template <bool GATHER>
__global__ void __launch_bounds__(256, 2)
gemm_relu_kernel(const float* __restrict__ A,
                 const float* __restrict__ h, const float* __restrict__ e,
                 const int* __restrict__ srcv, const int* __restrict__ dstv,
                 const float* __restrict__ Bt, const float* __restrict__ bias,
                 float* __restrict__ Y, int M, int N, int K) {
    __shared__ float As[8][132];          // padded: conflict-free k-major stores
    __shared__ float Bs[8][128];
    __shared__ int s_src[128], s_dst[128];

    int  tid = threadIdx.x;
    long m0  = (long)blockIdx.x * 128;
    int  n0  = blockIdx.y * 128;

    if (GATHER) {
        if (tid < 128) s_src[tid] = srcv[m0 + tid];
        else           s_dst[tid - 128] = dstv[m0 + (tid - 128)];
        __syncthreads();
    }

    int tx = tid & 15, ty = tid >> 4;
    int lm = tid >> 1, lk4 = (tid & 1) * 4;      // A-load: 1 float4 / thread
    int ln4 = (tid & 31) * 4, lbk = tid >> 5;    // B-load: 1 float4 / thread

    float acc[8][8];
    #pragma unroll
    for (int i = 0; i < 8; i++)
        #pragma unroll
        for (int j = 0; j < 8; j++) acc[i][j] = 0.f;

    for (int k0 = 0; k0 < K; k0 += 8) {
        float4 av;
        if (GATHER) {
            int f = k0 + lk4;
            const float* abase;
            if (f < D_H)            abase = h + (long)s_src[lm] * D_H + f;
            else if (f < 2 * D_H)   abase = h + (long)s_dst[lm] * D_H + (f - D_H);
            else                    abase = e + (m0 + lm) * D_E + (f - 2 * D_H);
            av = *(const float4*)abase;
        } else {
            av = *(const float4*)(A + (m0 + lm) * K + k0 + lk4);
        }
        float4 bv = *(const float4*)(Bt + (long)(k0 + lbk) * N + n0 + ln4);

        __syncthreads();
        As[lk4 + 0][lm] = av.x; As[lk4 + 1][lm] = av.y;
        As[lk4 + 2][lm] = av.z; As[lk4 + 3][lm] = av.w;
        *(float4*)&Bs[lbk][ln4] = bv;
        __syncthreads();

        #pragma unroll
        for (int kk = 0; kk < 8; kk++) {
            float a[8], b[8];
            *(float4*)&a[0] = *(const float4*)&As[kk][ty * 8];
            *(float4*)&a[4] = *(const float4*)&As[kk][ty * 8 + 4];
            *(float4*)&b[0] = *(const float4*)&Bs[kk][tx * 8];
            *(float4*)&b[4] = *(const float4*)&Bs[kk][tx * 8 + 4];
            #pragma unroll
            for (int i = 0; i < 8; i++)
                #pragma unroll
                for (int j = 0; j < 8; j++)
                    acc[i][j] += a[i] * b[j];
        }
    }

    float bvals[8];
    #pragma unroll
    for (int j = 0; j < 8; j++) bvals[j] = bias[n0 + tx * 8 + j];

    #pragma unroll
    for (int i = 0; i < 8; i++) {
        long row = m0 + ty * 8 + i;
        float4 v0, v1;
        v0.x = fmaxf(acc[i][0] + bvals[0], 0.f);
        v0.y = fmaxf(acc[i][1] + bvals[1], 0.f);
        v0.z = fmaxf(acc[i][2] + bvals[2], 0.f);
        v0.w = fmaxf(acc[i][3] + bvals[3], 0.f);
        v1.x = fmaxf(acc[i][4] + bvals[4], 0.f);
        v1.y = fmaxf(acc[i][5] + bvals[5], 0.f);
        v1.z = fmaxf(acc[i][6] + bvals[6], 0.f);
        v1.w = fmaxf(acc[i][7] + bvals[7], 0.f);
        *(float4*)&Y[row * N + n0 + tx * 8]     = v0;
        *(float4*)&Y[row * N + n0 + tx * 8 + 4] = v1;
    }
}

// ---------------- host launch sequence ---------------------------------------------
extern "C" void kernel_launch(void* const* d_in, const int* in_sizes, int n_in,
                              void* d_out, int out_size) {
    const float* h     = (const float*)d_in[0];
    const float* e     = (const float*)d_in[1];
    const int*   src   = (const int*)  d_in[2];
    const int*   dst   = (const int*)  d_in[3];
    const float* bn0_g = (const float*)d_in[4];
    const float* bn0_b = (const float*)d_in[5];
    const float* W1    = (const float*)d_in[6];
    const float* b1    = (const float*)d_in[7];
    const float* bn1_g = (const float*)d_in[8];
    const float* bn1_b = (const float*)d_in[9];
    const float* W2    = (const float*)d_in[10];
    const float* b2    = (const float*)d_in[11];
    const float* bn2_g = (const float*)d_in[12];
    const float* bn2_b = (const float*)d_in[13];
    const float* W3    = (const float*)d_in[14];
    const float* b3    = (const float*)d_in[15];
    float* out = (float*)d_out;

    int n_nodes = in_sizes[0] / D_H;
    int n_edges = in_sizes[2];
    float invM = 1.0f / (float)n_edges;

    float *y1, *y2, *sum0, *sq0, *sum1, *sq1, *sum2, *sq2;
    float *scale0, *shift0, *scale1, *shift1, *scale2, *shift2;
    float *W1t, *b1f, *W2t, *b2f;
    cudaGetSymbolAddress((void**)&y1, g_y1);
    cudaGetSymbolAddress((void**)&y2, g_y2);
    cudaGetSymbolAddress((void**)&sum0, g_sum0);
    cudaGetSymbolAddress((void**)&sq0,  g_sq0);
    cudaGetSymbolAddress((void**)&sum1, g_sum1);
    cudaGetSymbolAddress((void**)&sq1,  g_sq1);
    cudaGetSymbolAddress((void**)&sum2, g_sum2);
    cudaGetSymbolAddress((void**)&sq2,  g_sq2);
    cudaGetSymbolAddress((void**)&scale0, g_scale0);
    cudaGetSymbolAddress((void**)&shift0, g_shift0);
    cudaGetSymbolAddress((void**)&scale1, g_scale1);
    cudaGetSymbolAddress((void**)&shift1, g_shift1);
    cudaGetSymbolAddress((void**)&scale2, g_scale2);
    cudaGetSymbolAddress((void**)&shift2, g_shift2);
    cudaGetSymbolAddress((void**)&W1t, g_W1t);
    cudaGetSymbolAddress((void**)&b1f, g_b1f);
    cudaGetSymbolAddress((void**)&W2t, g_W2t);
    cudaGetSymbolAddress((void**)&b2f, g_b2f);

    // 1) zero accumulators + degree histograms
    zero_kernel<<<(n_nodes + 255) / 256, 256>>>(n_nodes);
    count_kernel<<<(n_edges + 255) / 256, 256>>>(src, dst, n_edges);

    // 2) BN0 statistics (degree-weighted node reduce + e column reduce)
    hstats_kernel<<<(n_nodes + NPB - 1) / NPB, 128>>>(h, n_nodes);
    estats_kernel<<<1024, 256>>>(e, n_edges);
    affine_kernel<<<(F0 + 127) / 128, 128>>>(sum0, sq0, bn0_g, bn0_b, scale0, shift0, F0, invM);

    // 3) fold BN0 into W1 (scaled + transposed) and b1
    foldT_kernel<<<(H1 * F0 + 255) / 256, 256>>>(W1, scale0, W1t, H1, F0);
    foldB_kernel<<<H1, 128>>>(W1, b1, shift0, b1f, F0);

    // 4) GEMM1: gathered edge features -> y1 = relu(x @ W1f^T + b1f)
    gemm_relu_kernel<true><<<dim3(n_edges / 128, H1 / 128), 256>>>(
        nullptr, h, e, src, dst, W1t, b1f, y1, n_edges, H1, F0);

    // 5) BN1 stats + fold into W2
    colstats_kernel<<<768, H1>>>(y1, sum1, sq1, n_edges, H1);
    affine_kernel<<<(H1 + 127) / 128, 128>>>(sum1, sq1, bn1_g, bn1_b, scale1, shift1, H1, invM);
    foldT_kernel<<<(H2 * H1 + 255) / 256, 256>>>(W2, scale1, W2t, H2, H1);
    foldB_kernel<<<H2, 128>>>(W2, b2, shift1, b2f, H1);

    // 6) GEMM2: y2 = relu(y1 @ W2f^T + b2f)
    gemm_relu_kernel<false><<<dim3(n_edges / 128, H2 / 128), 256>>>(
        y1, nullptr, nullptr, nullptr, nullptr, W2t, b2f, y2, n_edges, H2, H1);

    // 7) BN2 stats + fold into W3, final matvec
    colstats_kernel<<<768, H2>>>(y2, sum2, sq2, n_edges, H2);
    affine_kernel<<<1, 128>>>(sum2, sq2, bn2_g, bn2_b, scale2, shift2, H2, invM);
    fold3_kernel<<<1, 128>>>(W3, b3);
    out_kernel<<<(n_edges + 7) / 8, 256>>>(y2, out, n_edges);
}

// round 7
// speedup vs baseline: 1.4612x; 1.4612x over previous
#include <cuda_runtime.h>
#include <cuda_bf16.h>
#include <cstdint>
#include <math.h>

#define D_H   128
#define D_E   64
#define F0    320
#define H1    256
#define H2    128
#define MAX_NODES 50000
#define MAX_EDGES 800000

// ======================= helpers ==================================================
__device__ __forceinline__ uint32_t smem_to_u32(const void* p) {
    uint32_t a;
    asm("{ .reg .u64 t; cvta.to.shared.u64 t, %1; cvt.u32.u64 %0, t; }" : "=r"(a) : "l"(p));
    return a;
}
#define SWZ(off) ((off) ^ (((off) >> 3) & 0x70))

__device__ __forceinline__ void ldsm4(uint32_t* r, uint32_t addr) {
    asm volatile("ldmatrix.sync.aligned.m8n8.x4.shared.b16 {%0,%1,%2,%3}, [%4];"
                 : "=r"(r[0]), "=r"(r[1]), "=r"(r[2]), "=r"(r[3]) : "r"(addr));
}
__device__ __forceinline__ void mma_bf16(float* d, const uint32_t* a, uint32_t b0, uint32_t b1) {
    asm volatile("mma.sync.aligned.m16n8k16.row.col.f32.bf16.bf16.f32 "
                 "{%0,%1,%2,%3}, {%4,%5,%6,%7}, {%8,%9}, {%0,%1,%2,%3};"
                 : "+f"(d[0]), "+f"(d[1]), "+f"(d[2]), "+f"(d[3])
                 : "r"(a[0]), "r"(a[1]), "r"(a[2]), "r"(a[3]), "r"(b0), "r"(b1));
}
__device__ __forceinline__ void split_pair(float x, float y, uint32_t& hi, uint32_t& lo) {
    __nv_bfloat162 h = __floats2bfloat162_rn(x, y);
    float2 hf = __bfloat1622float2(h);
    __nv_bfloat162 l = __floats2bfloat162_rn(x - hf.x, y - hf.y);
    hi = *reinterpret_cast<uint32_t*>(&h);
    lo = *reinterpret_cast<uint32_t*>(&l);
}

// ======================= device scratch ==========================================
__device__ __nv_bfloat16 g_y1h[(size_t)MAX_EDGES * H1];
__device__ __nv_bfloat16 g_y1l[(size_t)MAX_EDGES * H1];
__device__ __nv_bfloat16 g_y2h[(size_t)MAX_EDGES * H2];
__device__ __nv_bfloat16 g_y2l[(size_t)MAX_EDGES * H2];
__device__ __nv_bfloat16 g_W1h[H1 * F0], g_W1l[H1 * F0];
__device__ __nv_bfloat16 g_W2h[H2 * H1], g_W2l[H2 * H1];
__device__ int   g_cnt_src[MAX_NODES];
__device__ int   g_cnt_dst[MAX_NODES];
__device__ float g_sum0[F0], g_sq0[F0];
__device__ float g_sum1[H1], g_sq1[H1];
__device__ float g_sum2[H2], g_sq2[H2];
__device__ float g_scale0[F0], g_shift0[F0];
__device__ float g_scale1[H1], g_shift1[H1];
__device__ float g_scale2[H2], g_shift2[H2];
__device__ float g_b1f[H1], g_b2f[H2];
__device__ float g_W3f[H2];
__device__ float g_b3f[1];

// ======================= setup / stats kernels ===================================
__global__ void zero_kernel(int n_nodes) {
    int i = blockIdx.x * blockDim.x + threadIdx.x;
    if (i < n_nodes) { g_cnt_src[i] = 0; g_cnt_dst[i] = 0; }
    if (i < F0) { g_sum0[i] = 0.f; g_sq0[i] = 0.f; }
    if (i < H1) { g_sum1[i] = 0.f; g_sq1[i] = 0.f; }
    if (i < H2) { g_sum2[i] = 0.f; g_sq2[i] = 0.f; }
}

__global__ void count_kernel(const int* __restrict__ src, const int* __restrict__ dst, int n) {
    int i = blockIdx.x * blockDim.x + threadIdx.x;
    if (i < n) {
        atomicAdd(&g_cnt_src[src[i]], 1);
        atomicAdd(&g_cnt_dst[dst[i]], 1);
    }
}

#define NPB 256
__global__ void hstats_kernel(const float* __restrict__ h, int n_nodes) {
    __shared__ float c1s[NPB], c2s[NPB];
    int t  = threadIdx.x;
    int v0 = blockIdx.x * NPB;
    for (int i = t; i < NPB; i += 128) {
        int v = v0 + i;
        c1s[i] = (v < n_nodes) ? (float)g_cnt_src[v] : 0.f;
        c2s[i] = (v < n_nodes) ? (float)g_cnt_dst[v] : 0.f;
    }
    __syncthreads();
    float s1 = 0.f, q1 = 0.f, s2 = 0.f, q2 = 0.f;
    int lim = n_nodes - v0; if (lim > NPB) lim = NPB;
    for (int i = 0; i < lim; i++) {
        float x  = h[(long)(v0 + i) * D_H + t];
        float x2 = x * x;
        s1 += c1s[i] * x; q1 += c1s[i] * x2;
        s2 += c2s[i] * x; q2 += c2s[i] * x2;
    }
    atomicAdd(&g_sum0[t], s1);          atomicAdd(&g_sq0[t], q1);
    atomicAdd(&g_sum0[D_H + t], s2);    atomicAdd(&g_sq0[D_H + t], q2);
}

__global__ void estats_kernel(const float* __restrict__ e, int M) {
    int c4 = threadIdx.x & 15, r = threadIdx.x >> 4;
    float s0=0,s1=0,s2=0,s3=0,q0=0,q1=0,q2=0,q3=0;
    for (long row = (long)blockIdx.x * 16 + r; row < M; row += (long)gridDim.x * 16) {
        float4 v = ((const float4*)(e + row * D_E))[c4];
        s0 += v.x; q0 += v.x*v.x;
        s1 += v.y; q1 += v.y*v.y;
        s2 += v.z; q2 += v.z*v.z;
        s3 += v.w; q3 += v.w*v.w;
    }
    int base = 2 * D_H + c4 * 4;
    atomicAdd(&g_sum0[base+0], s0); atomicAdd(&g_sq0[base+0], q0);
    atomicAdd(&g_sum0[base+1], s1); atomicAdd(&g_sq0[base+1], q1);
    atomicAdd(&g_sum0[base+2], s2); atomicAdd(&g_sq0[base+2], q2);
    atomicAdd(&g_sum0[base+3], s3); atomicAdd(&g_sq0[base+3], q3);
}

template <int N>
__global__ void colstats_bf16_kernel(const __nv_bfloat16* __restrict__ Xh,
                                     const __nv_bfloat16* __restrict__ Xl,
                                     float* __restrict__ sum, float* __restrict__ sq, int M) {
    constexpr int C2 = N / 2;
    constexpr int RPB = 256 / C2;
    int c2 = threadIdx.x % C2;
    int r0 = threadIdx.x / C2;
    float s0=0, s1=0, q0=0, q1=0;
    const uint32_t* Ph = (const uint32_t*)Xh;
    const uint32_t* Pl = (const uint32_t*)Xl;
    for (long r = (long)blockIdx.x * RPB + r0; r < M; r += (long)gridDim.x * RPB) {
        uint32_t vh = Ph[r * C2 + c2], vl = Pl[r * C2 + c2];
        float2 fh = __bfloat1622float2(*reinterpret_cast<__nv_bfloat162*>(&vh));
        float2 fl = __bfloat1622float2(*reinterpret_cast<__nv_bfloat162*>(&vl));
        float x0 = fh.x + fl.x, x1 = fh.y + fl.y;
        s0 += x0; q0 += x0*x0; s1 += x1; q1 += x1*x1;
    }
    atomicAdd(&sum[2*c2],   s0); atomicAdd(&sq[2*c2],   q0);
    atomicAdd(&sum[2*c2+1], s1); atomicAdd(&sq[2*c2+1], q1);
}

__global__ void affine_kernel(const float* __restrict__ sum, const float* __restrict__ sq,
                              const float* __restrict__ g, const float* __restrict__ b,
                              float* __restrict__ scale, float* __restrict__ shift,
                              int K, float invM) {
    int j = blockIdx.x * blockDim.x + threadIdx.x;
    if (j < K) {
        float mean = sum[j] * invM;
        float var  = sq[j] * invM - mean * mean;
        float sc   = g[j] * rsqrtf(var + 1e-5f);
        scale[j] = sc;
        shift[j] = b[j] - mean * sc;
    }
}

__global__ void foldW_kernel(const float* __restrict__ W, const float* __restrict__ scale,
                             __nv_bfloat16* __restrict__ Wh, __nv_bfloat16* __restrict__ Wl,
                             int N, int K) {
    int idx = blockIdx.x * blockDim.x + threadIdx.x;
    if (idx < N * K) {
        int k = idx % K;
        float v = W[idx] * scale[k];
        __nv_bfloat16 hi = __float2bfloat16(v);
        Wh[idx] = hi;
        Wl[idx] = __float2bfloat16(v - __bfloat162float(hi));
    }
}

__global__ void foldB_kernel(const float* __restrict__ W, const float* __restrict__ bvec,
                             const float* __restrict__ shift, float* __restrict__ bout, int K) {
    int o = blockIdx.x, t = threadIdx.x;
    float s = 0.f;
    for (int j = t; j < K; j += 128) s += W[(long)o * K + j] * shift[j];
    __shared__ float red[128];
    red[t] = s; __syncthreads();
    for (int w = 64; w > 0; w >>= 1) { if (t < w) red[t] += red[t + w]; __syncthreads(); }
    if (t == 0) bout[o] = bvec[o] + red[0];
}

__global__ void fold3_kernel(const float* __restrict__ W3, const float* __restrict__ b3) {
    int t = threadIdx.x;
    float w = W3[t];
    g_W3f[t] = w * g_scale2[t];
    __shared__ float red[128];
    red[t] = w * g_shift2[t]; __syncthreads();
    for (int w2 = 64; w2 > 0; w2 >>= 1) { if (t < w2) red[t] += red[t + w2]; __syncthreads(); }
    if (t == 0) g_b3f[0] = b3[0] + red[0];
}

__global__ void out_kernel(const __nv_bfloat16* __restrict__ Yh,
                           const __nv_bfloat16* __restrict__ Yl,
                           float* __restrict__ out, int M) {
    int warp = (blockIdx.x * blockDim.x + threadIdx.x) >> 5;
    int lane = threadIdx.x & 31;
    if (warp >= M) return;
    const uint32_t* rh = (const uint32_t*)(Yh + (long)warp * H2);
    const uint32_t* rl = (const uint32_t*)(Yl + (long)warp * H2);
    float s = 0.f;
    #pragma unroll
    for (int g = 0; g < 2; g++) {
        uint32_t vh = rh[lane + 32*g], vl = rl[lane + 32*g];
        float2 fh = __bfloat1622float2(*reinterpret_cast<__nv_bfloat162*>(&vh));
        float2 fl = __bfloat1622float2(*reinterpret_cast<__nv_bfloat162*>(&vl));
        int c = 2 * (lane + 32*g);
        s += (fh.x + fl.x) * g_W3f[c] + (fh.y + fl.y) * g_W3f[c + 1];
    }
    #pragma unroll
    for (int o = 16; o > 0; o >>= 1) s += __shfl_down_sync(0xffffffffu, s, o);
    if (lane == 0) out[warp] = s + g_b3f[0];
}

// ======================= mma.sync bf16x3 GEMM =====================================
// Y[m][n] = relu( sum_k A[m][k]*B[n][k] + bias[n] ), A/B as bf16 hi+lo planes,
// 3 tensor products (hh + hl + lh) with fp32 accumulation.
// CTA tile: M=128, N=128. K staged in 64-element chunks through SMEM (SW swizzle).
// 8 warps: wm = warp>>1 (M quarter of 32), wn = warp&1 (N half of 64).
// GATHER: A row m = concat(h[src[m]], h[dst[m]], e[m]) fp32, split on the fly.

template<bool GATHER, int KTOT>
__global__ void __launch_bounds__(256, 1)
gemm_mma_kernel(const float* __restrict__ hsrc, const float* __restrict__ esrc,
                const int* __restrict__ srcv, const int* __restrict__ dstv,
                const __nv_bfloat16* __restrict__ Ah, const __nv_bfloat16* __restrict__ Al,
                const __nv_bfloat16* __restrict__ Bh, const __nv_bfloat16* __restrict__ Bl,
                const float* __restrict__ bias,
                __nv_bfloat16* __restrict__ Yh, __nv_bfloat16* __restrict__ Yl,
                int NTOT)
{
    constexpr int NCH = KTOT / 64;
    constexpr int PSZ = 128 * 128;     // bytes per plane (128 rows x 128B)

    extern __shared__ char smem[];
    __shared__ int s_src[128], s_dst[128];

    const uint32_t sbase = smem_to_u32(smem);
    const uint32_t sAh = sbase, sAl = sbase + PSZ, sBh = sbase + 2*PSZ, sBl = sbase + 3*PSZ;

    int tid = threadIdx.x, lane = tid & 31, warp = tid >> 5;
    int wm = warp >> 1, wn = warp & 1;
    long m0 = (long)blockIdx.x * 128;
    int  n0 = blockIdx.y * 128;

    const __nv_bfloat16* Bh_ = Bh + (long)n0 * KTOT;
    const __nv_bfloat16* Bl_ = Bl + (long)n0 * KTOT;

    if (GATHER) {
        if (tid < 128) s_src[tid] = srcv[m0 + tid];
        else           s_dst[tid - 128] = dstv[m0 + (tid - 128)];
        __syncthreads();
    }

    // ---- stage-loader lane mapping ----
    int rowA = tid >> 1, hfA = tid & 1;         // A: 128 rows, 2 half-rows of 64B
    int rowB = tid >> 1, hfB = tid & 1;         // B: same

    float4 pa[8];                                // GATHER prefetch (32 fp32)
    uint4  pah[4], pal[4];                       // non-gather prefetch (64B/plane)
    uint4  pbh[4], pbl[4];                       // B prefetch (64B/plane)

    auto load_chunk = [&](int c) {
        if (GATHER) {
            const float* p;
            if (c < 4) {
                int node = (c < 2) ? s_src[rowA] : s_dst[rowA];
                p = hsrc + (long)node * D_H + (c & 1) * 64 + hfA * 32;
            } else {
                p = esrc + (m0 + rowA) * D_E + hfA * 32;
            }
            #pragma unroll
            for (int i = 0; i < 8; i++) pa[i] = *(const float4*)(p + i * 4);
        } else {
            const uint4* ph = (const uint4*)(Ah + (m0 + rowA) * KTOT + c * 64 + hfA * 32);
            const uint4* pl = (const uint4*)(Al + (m0 + rowA) * KTOT + c * 64 + hfA * 32);
            #pragma unroll
            for (int j = 0; j < 4; j++) { pah[j] = ph[j]; pal[j] = pl[j]; }
        }
        const uint4* qh = (const uint4*)(Bh_ + (long)rowB * KTOT + c * 64 + hfB * 32);
        const uint4* ql = (const uint4*)(Bl_ + (long)rowB * KTOT + c * 64 + hfB * 32);
        #pragma unroll
        for (int j = 0; j < 4; j++) { pbh[j] = qh[j]; pbl[j] = ql[j]; }
    };

    auto store_chunk = [&]() {
        if (GATHER) {
            #pragma unroll
            for (int i = 0; i < 8; i++) {
                uint32_t off = SWZ((uint32_t)(rowA * 128 + hfA * 64 + i * 8));
                uint2 uh, ul;
                split_pair(pa[i].x, pa[i].y, uh.x, ul.x);
                split_pair(pa[i].z, pa[i].w, uh.y, ul.y);
                *(uint2*)(smem + off)       = uh;
                *(uint2*)(smem + PSZ + off) = ul;
            }
        } else {
            #pragma unroll
            for (int j = 0; j < 4; j++) {
                uint32_t off = SWZ((uint32_t)(rowA * 128 + hfA * 64 + j * 16));
                *(uint4*)(smem + off)       = pah[j];
                *(uint4*)(smem + PSZ + off) = pal[j];
            }
        }
        #pragma unroll
        for (int j = 0; j < 4; j++) {
            uint32_t off = SWZ((uint32_t)(rowB * 128 + hfB * 64 + j * 16));
            *(uint4*)(smem + 2*PSZ + off) = pbh[j];
            *(uint4*)(smem + 3*PSZ + off) = pbl[j];
        }
    };

    float acc[2][8][4];
    #pragma unroll
    for (int i = 0; i < 2; i++)
        #pragma unroll
        for (int j = 0; j < 8; j++)
            #pragma unroll
            for (int q = 0; q < 4; q++) acc[i][j][q] = 0.f;

    load_chunk(0);
    store_chunk();
    __syncthreads();

    for (int c = 0; c < NCH; c++) {
        if (c + 1 < NCH) load_chunk(c + 1);

        // ---- compute chunk c ----
        #pragma unroll
        for (int kk = 0; kk < 4; kk++) {
            uint32_t ah[2][4], al[2][4], bh[4][4], bl[4][4];
            uint32_t colb = (uint32_t)(kk * 32 + ((lane >> 4) << 4));
            int rA = wm * 32 + (lane & 15);
            #pragma unroll
            for (int mt = 0; mt < 2; mt++) {
                uint32_t off = SWZ((uint32_t)((rA + mt * 16) * 128) + colb);
                ldsm4(ah[mt], sAh + off);
                ldsm4(al[mt], sAl + off);
            }
            int rB = wn * 64 + (lane & 15);
            #pragma unroll
            for (int q = 0; q < 4; q++) {
                uint32_t off = SWZ((uint32_t)((rB + q * 16) * 128) + colb);
                ldsm4(bh[q], sBh + off);
                ldsm4(bl[q], sBl + off);
            }
            // hh
            #pragma unroll
            for (int mt = 0; mt < 2; mt++)
                #pragma unroll
                for (int q = 0; q < 4; q++) {
                    mma_bf16(acc[mt][2*q],   ah[mt], bh[q][0], bh[q][2]);
                    mma_bf16(acc[mt][2*q+1], ah[mt], bh[q][1], bh[q][3]);
                }
            // hl
            #pragma unroll
            for (int mt = 0; mt < 2; mt++)
                #pragma unroll
                for (int q = 0; q < 4; q++) {
                    mma_bf16(acc[mt][2*q],   ah[mt], bl[q][0], bl[q][2]);
                    mma_bf16(acc[mt][2*q+1], ah[mt], bl[q][1], bl[q][3]);
                }
            // lh
            #pragma unroll
            for (int mt = 0; mt < 2; mt++)
                #pragma unroll
                for (int q = 0; q < 4; q++) {
                    mma_bf16(acc[mt][2*q],   al[mt], bh[q][0], bh[q][2]);
                    mma_bf16(acc[mt][2*q+1], al[mt], bh[q][1], bh[q][3]);
                }
        }

        if (c + 1 < NCH) {
            __syncthreads();
            store_chunk();
            __syncthreads();
        }
    }

    // ---- epilogue: bias + ReLU + bf16-pair split ----
    uint32_t* Yh32 = (uint32_t*)Yh;
    uint32_t* Yl32 = (uint32_t*)Yl;
    int lane4 = lane >> 2, lanem = lane & 3;
    #pragma unroll
    for (int mt = 0; mt < 2; mt++) {
        #pragma unroll
        for (int nt = 0; nt < 8; nt++) {
            int col = wn * 64 + nt * 8 + lanem * 2;
            float b0v = __ldg(&bias[n0 + col]), b1v = __ldg(&bias[n0 + col + 1]);
            long r0 = m0 + wm * 32 + mt * 16 + lane4;
            long r1 = r0 + 8;
            uint32_t hi, lo;
            float f0 = fmaxf(acc[mt][nt][0] + b0v, 0.f);
            float f1 = fmaxf(acc[mt][nt][1] + b1v, 0.f);
            split_pair(f0, f1, hi, lo);
            long idx0 = (r0 * NTOT + n0 + col) >> 1;
            Yh32[idx0] = hi; Yl32[idx0] = lo;
            float f2 = fmaxf(acc[mt][nt][2] + b0v, 0.f);
            float f3 = fmaxf(acc[mt][nt][3] + b1v, 0.f);
            split_pair(f2, f3, hi, lo);
            long idx1 = (r1 * NTOT + n0 + col) >> 1;
            Yh32[idx1] = hi; Yl32[idx1] = lo;
        }
    }
}

// ======================= host launch sequence =====================================
extern "C" void kernel_launch(void* const* d_in, const int* in_sizes, int n_in,
                              void* d_out, int out_size) {
    const float* h     = (const float*)d_in[0];
    const float* e     = (const float*)d_in[1];
    const int*   src   = (const int*)  d_in[2];
    const int*   dst   = (const int*)  d_in[3];
    const float* bn0_g = (const float*)d_in[4];
    const float* bn0_b = (const float*)d_in[5];
    const float* W1    = (const float*)d_in[6];
    const float* b1    = (const float*)d_in[7];
    const float* bn1_g = (const float*)d_in[8];
    const float* bn1_b = (const float*)d_in[9];
    const float* W2    = (const float*)d_in[10];
    const float* b2    = (const float*)d_in[11];
    const float* bn2_g = (const float*)d_in[12];
    const float* bn2_b = (const float*)d_in[13];
    const float* W3    = (const float*)d_in[14];
    const float* b3    = (const float*)d_in[15];
    float* out = (float*)d_out;

    int n_nodes = in_sizes[0] / D_H;
    int n_edges = in_sizes[2];
    float invM = 1.0f / (float)n_edges;
    int ntiles = n_edges / 128;

    __nv_bfloat16 *y1h, *y1l, *y2h, *y2l, *w1h, *w1l, *w2h, *w2l;
    float *sum0, *sq0, *sum1, *sq1, *sum2, *sq2;
    float *scale0, *shift0, *scale1, *shift1, *scale2, *shift2, *b1f, *b2f;
    cudaGetSymbolAddress((void**)&y1h, g_y1h);
    cudaGetSymbolAddress((void**)&y1l, g_y1l);
    cudaGetSymbolAddress((void**)&y2h, g_y2h);
    cudaGetSymbolAddress((void**)&y2l, g_y2l);
    cudaGetSymbolAddress((void**)&w1h, g_W1h);
    cudaGetSymbolAddress((void**)&w1l, g_W1l);
    cudaGetSymbolAddress((void**)&w2h, g_W2h);
    cudaGetSymbolAddress((void**)&w2l, g_W2l);
    cudaGetSymbolAddress((void**)&sum0, g_sum0);
    cudaGetSymbolAddress((void**)&sq0,  g_sq0);
    cudaGetSymbolAddress((void**)&sum1, g_sum1);
    cudaGetSymbolAddress((void**)&sq1,  g_sq1);
    cudaGetSymbolAddress((void**)&sum2, g_sum2);
    cudaGetSymbolAddress((void**)&sq2,  g_sq2);
    cudaGetSymbolAddress((void**)&scale0, g_scale0);
    cudaGetSymbolAddress((void**)&shift0, g_shift0);
    cudaGetSymbolAddress((void**)&scale1, g_scale1);
    cudaGetSymbolAddress((void**)&shift1, g_shift1);
    cudaGetSymbolAddress((void**)&scale2, g_scale2);
    cudaGetSymbolAddress((void**)&shift2, g_shift2);
    cudaGetSymbolAddress((void**)&b1f, g_b1f);
    cudaGetSymbolAddress((void**)&b2f, g_b2f);

    constexpr int SMEM_SZ = 4 * 128 * 128;   // 64 KB
    cudaFuncSetAttribute(gemm_mma_kernel<true, 320>,
                         cudaFuncAttributeMaxDynamicSharedMemorySize, SMEM_SZ);
    cudaFuncSetAttribute(gemm_mma_kernel<false, 256>,
                         cudaFuncAttributeMaxDynamicSharedMemorySize, SMEM_SZ);

    // 1) BN0 stats via degree histogram + node-weighted reduce + e column reduce
    zero_kernel<<<(n_nodes + 255) / 256, 256>>>(n_nodes);
    count_kernel<<<(n_edges + 255) / 256, 256>>>(src, dst, n_edges);
    hstats_kernel<<<(n_nodes + NPB - 1) / NPB, 128>>>(h, n_nodes);
    estats_kernel<<<1024, 256>>>(e, n_edges);
    affine_kernel<<<(F0 + 127) / 128, 128>>>(sum0, sq0, bn0_g, bn0_b, scale0, shift0, F0, invM);

    // 2) fold BN0 into W1 (bf16 hi/lo planes) + bias
    foldW_kernel<<<(H1 * F0 + 255) / 256, 256>>>(W1, scale0, w1h, w1l, H1, F0);
    foldB_kernel<<<H1, 128>>>(W1, b1, shift0, b1f, F0);

    // 3) GEMM1 (mma.sync bf16x3): y1 = relu(gather(x) @ W1f^T + b1f)
    gemm_mma_kernel<true, 320><<<dim3(ntiles, 2), 256, SMEM_SZ>>>(
        h, e, src, dst, nullptr, nullptr, w1h, w1l, b1f, y1h, y1l, H1);

    // 4) BN1 stats + fold into W2
    colstats_bf16_kernel<H1><<<2048, 256>>>(y1h, y1l, sum1, sq1, n_edges);
    affine_kernel<<<(H1 + 127) / 128, 128>>>(sum1, sq1, bn1_g, bn1_b, scale1, shift1, H1, invM);
    foldW_kernel<<<(H2 * H1 + 255) / 256, 256>>>(W2, scale1, w2h, w2l, H2, H1);
    foldB_kernel<<<H2, 128>>>(W2, b2, shift1, b2f, H1);

    // 5) GEMM2: y2 = relu(y1 @ W2f^T + b2f)
    gemm_mma_kernel<false, 256><<<dim3(ntiles, 1), 256, SMEM_SZ>>>(
        nullptr, nullptr, nullptr, nullptr, y1h, y1l, w2h, w2l, b2f, y2h, y2l, H2);

    // 6) BN2 stats + fold into W3, final matvec
    colstats_bf16_kernel<H2><<<2048, 256>>>(y2h, y2l, sum2, sq2, n_edges);
    affine_kernel<<<1, 128>>>(sum2, sq2, bn2_g, bn2_b, scale2, shift2, H2, invM);
    fold3_kernel<<<1, 128>>>(W3, b3);
    out_kernel<<<(n_edges + 7) / 8, 256>>>(y2h, y2l, out, n_edges);
}

// round 8
// speedup vs baseline: 1.7612x; 1.2053x over previous
#include <cuda_runtime.h>
#include <cuda_bf16.h>
#include <cstdint>
#include <math.h>

#define D_H   128
#define D_E   64
#define F0    320
#define H1    256
#define H2    128
#define MAX_NODES 50000
#define MAX_EDGES 800000

// ======================= helpers ==================================================
__device__ __forceinline__ uint32_t smem_to_u32(const void* p) {
    uint32_t a;
    asm("{ .reg .u64 t; cvta.to.shared.u64 t, %1; cvt.u32.u64 %0, t; }" : "=r"(a) : "l"(p));
    return a;
}
#define SWZ(off) ((off) ^ (((off) >> 3) & 0x70))

__device__ __forceinline__ void ldsm4(uint32_t* r, uint32_t addr) {
    asm volatile("ldmatrix.sync.aligned.m8n8.x4.shared.b16 {%0,%1,%2,%3}, [%4];"
                 : "=r"(r[0]), "=r"(r[1]), "=r"(r[2]), "=r"(r[3]) : "r"(addr));
}
__device__ __forceinline__ void mma_bf16(float* d, const uint32_t* a, uint32_t b0, uint32_t b1) {
    asm volatile("mma.sync.aligned.m16n8k16.row.col.f32.bf16.bf16.f32 "
                 "{%0,%1,%2,%3}, {%4,%5,%6,%7}, {%8,%9}, {%0,%1,%2,%3};"
                 : "+f"(d[0]), "+f"(d[1]), "+f"(d[2]), "+f"(d[3])
                 : "r"(a[0]), "r"(a[1]), "r"(a[2]), "r"(a[3]), "r"(b0), "r"(b1));
}
__device__ __forceinline__ void split_pair(float x, float y, uint32_t& hi, uint32_t& lo) {
    __nv_bfloat162 h = __floats2bfloat162_rn(x, y);
    float2 hf = __bfloat1622float2(h);
    __nv_bfloat162 l = __floats2bfloat162_rn(x - hf.x, y - hf.y);
    hi = *reinterpret_cast<uint32_t*>(&h);
    lo = *reinterpret_cast<uint32_t*>(&l);
}

// ======================= device scratch ==========================================
__device__ __nv_bfloat16 g_y1h[(size_t)MAX_EDGES * H1];
__device__ __nv_bfloat16 g_y1l[(size_t)MAX_EDGES * H1];
__device__ float         g_y2f[(size_t)MAX_EDGES * H2];
__device__ __nv_bfloat16 g_W1h[H1 * F0], g_W1l[H1 * F0];
__device__ __nv_bfloat16 g_W2h[H2 * H1], g_W2l[H2 * H1];
__device__ int   g_cnt_src[MAX_NODES];
__device__ int   g_cnt_dst[MAX_NODES];
__device__ float g_sum0[F0], g_sq0[F0];
__device__ float g_sum1[H1], g_sq1[H1];
__device__ float g_sum2[H2], g_sq2[H2];
__device__ float g_scale0[F0], g_shift0[F0];
__device__ float g_scale1[H1], g_shift1[H1];
__device__ float g_scale2[H2], g_shift2[H2];
__device__ float g_b1f[H1], g_b2f[H2];
__device__ float g_W3f[H2];
__device__ float g_b3f[1];

// ======================= setup / stats kernels ===================================
__global__ void zero_kernel(int n_nodes) {
    int i = blockIdx.x * blockDim.x + threadIdx.x;
    if (i < n_nodes) { g_cnt_src[i] = 0; g_cnt_dst[i] = 0; }
    if (i < F0) { g_sum0[i] = 0.f; g_sq0[i] = 0.f; }
    if (i < H1) { g_sum1[i] = 0.f; g_sq1[i] = 0.f; }
    if (i < H2) { g_sum2[i] = 0.f; g_sq2[i] = 0.f; }
}

__global__ void count_kernel(const int* __restrict__ src, const int* __restrict__ dst, int n) {
    int i = blockIdx.x * blockDim.x + threadIdx.x;
    if (i < n) {
        atomicAdd(&g_cnt_src[src[i]], 1);
        atomicAdd(&g_cnt_dst[dst[i]], 1);
    }
}

#define NPB 256
__global__ void hstats_kernel(const float* __restrict__ h, int n_nodes) {
    __shared__ float c1s[NPB], c2s[NPB];
    int t  = threadIdx.x;
    int v0 = blockIdx.x * NPB;
    for (int i = t; i < NPB; i += 128) {
        int v = v0 + i;
        c1s[i] = (v < n_nodes) ? (float)g_cnt_src[v] : 0.f;
        c2s[i] = (v < n_nodes) ? (float)g_cnt_dst[v] : 0.f;
    }
    __syncthreads();
    float s1 = 0.f, q1 = 0.f, s2 = 0.f, q2 = 0.f;
    int lim = n_nodes - v0; if (lim > NPB) lim = NPB;
    for (int i = 0; i < lim; i++) {
        float x  = h[(long)(v0 + i) * D_H + t];
        float x2 = x * x;
        s1 += c1s[i] * x; q1 += c1s[i] * x2;
        s2 += c2s[i] * x; q2 += c2s[i] * x2;
    }
    atomicAdd(&g_sum0[t], s1);          atomicAdd(&g_sq0[t], q1);
    atomicAdd(&g_sum0[D_H + t], s2);    atomicAdd(&g_sq0[D_H + t], q2);
}

// e column stats: 4 independent load streams for MLP, block smem reduce, few atomics.
__global__ void estats_kernel(const float* __restrict__ e, int M) {
    __shared__ float ss[4][64], sq_[4][64];
    int t = threadIdx.x & 63, r = threadIdx.x >> 6;
    long stride = (long)gridDim.x * 4;
    long row = (long)blockIdx.x * 4 + r;
    float sA = 0, qA = 0, sB = 0, qB = 0;
    long rlim = (long)M - 3 * stride;
    for (; row < rlim; row += 4 * stride) {
        float x0 = e[row * D_E + t];
        float x1 = e[(row + stride) * D_E + t];
        float x2 = e[(row + 2 * stride) * D_E + t];
        float x3 = e[(row + 3 * stride) * D_E + t];
        sA += x0 + x1; qA += x0 * x0 + x1 * x1;
        sB += x2 + x3; qB += x2 * x2 + x3 * x3;
    }
    for (; row < M; row += stride) { float x = e[row * D_E + t]; sA += x; qA += x * x; }
    ss[r][t] = sA + sB; sq_[r][t] = qA + qB;
    __syncthreads();
    if (threadIdx.x < 64) {
        float S = ss[0][t] + ss[1][t] + ss[2][t] + ss[3][t];
        float Q = sq_[0][t] + sq_[1][t] + sq_[2][t] + sq_[3][t];
        atomicAdd(&g_sum0[2 * D_H + t], S);
        atomicAdd(&g_sq0 [2 * D_H + t], Q);
    }
}

__global__ void affine_kernel(const float* __restrict__ sum, const float* __restrict__ sq,
                              const float* __restrict__ g, const float* __restrict__ b,
                              float* __restrict__ scale, float* __restrict__ shift,
                              int K, float invM) {
    int j = blockIdx.x * blockDim.x + threadIdx.x;
    if (j < K) {
        float mean = sum[j] * invM;
        float var  = sq[j] * invM - mean * mean;
        float sc   = g[j] * rsqrtf(var + 1e-5f);
        scale[j] = sc;
        shift[j] = b[j] - mean * sc;
    }
}

__global__ void foldW_kernel(const float* __restrict__ W, const float* __restrict__ scale,
                             __nv_bfloat16* __restrict__ Wh, __nv_bfloat16* __restrict__ Wl,
                             int N, int K) {
    int idx = blockIdx.x * blockDim.x + threadIdx.x;
    if (idx < N * K) {
        int k = idx % K;
        float v = W[idx] * scale[k];
        __nv_bfloat16 hi = __float2bfloat16(v);
        Wh[idx] = hi;
        Wl[idx] = __float2bfloat16(v - __bfloat162float(hi));
    }
}

__global__ void foldB_kernel(const float* __restrict__ W, const float* __restrict__ bvec,
                             const float* __restrict__ shift, float* __restrict__ bout, int K) {
    int o = blockIdx.x, t = threadIdx.x;
    float s = 0.f;
    for (int j = t; j < K; j += 128) s += W[(long)o * K + j] * shift[j];
    __shared__ float red[128];
    red[t] = s; __syncthreads();
    for (int w = 64; w > 0; w >>= 1) { if (t < w) red[t] += red[t + w]; __syncthreads(); }
    if (t == 0) bout[o] = bvec[o] + red[0];
}

__global__ void fold3_kernel(const float* __restrict__ W3, const float* __restrict__ b3) {
    int t = threadIdx.x;
    float w = W3[t];
    g_W3f[t] = w * g_scale2[t];
    __shared__ float red[128];
    red[t] = w * g_shift2[t]; __syncthreads();
    for (int w2 = 64; w2 > 0; w2 >>= 1) { if (t < w2) red[t] += red[t + w2]; __syncthreads(); }
    if (t == 0) g_b3f[0] = b3[0] + red[0];
}

__global__ void out_kernel(const float* __restrict__ Y2, float* __restrict__ out, int M) {
    int warp = (blockIdx.x * blockDim.x + threadIdx.x) >> 5;
    int lane = threadIdx.x & 31;
    if (warp >= M) return;
    float4 v = ((const float4*)(Y2 + (long)warp * H2))[lane];
    int c = lane * 4;
    float s = v.x * g_W3f[c] + v.y * g_W3f[c + 1] + v.z * g_W3f[c + 2] + v.w * g_W3f[c + 3];
    #pragma unroll
    for (int o = 16; o > 0; o >>= 1) s += __shfl_down_sync(0xffffffffu, s, o);
    if (lane == 0) out[warp] = s + g_b3f[0];
}

// ======================= mma.sync bf16x3 GEMM =====================================
// Y[m][n] = relu( sum_k A[m][k]*B[n][k] + bias[n] ), A/B as bf16 hi+lo planes,
// 3 tensor products (hh + hl + lh) with fp32 accumulation.
// CTA tile M=128, N=128; K staged in 64-element chunks; grid = (N-blocks, M-tiles).
// Epilogue: column sum/sumsq fused (shfl + smem + global atomics) and smem-staged
// coalesced stores. OUTPAIR: bf16 hi/lo planes; else fp32 plane.

template<bool GATHER, int KTOT, int NTOT, bool OUTPAIR>
__global__ void __launch_bounds__(256, 1)
gemm_mma_kernel(const float* __restrict__ hsrc, const float* __restrict__ esrc,
                const int* __restrict__ srcv, const int* __restrict__ dstv,
                const __nv_bfloat16* __restrict__ Ah, const __nv_bfloat16* __restrict__ Al,
                const __nv_bfloat16* __restrict__ Bh, const __nv_bfloat16* __restrict__ Bl,
                const float* __restrict__ bias,
                __nv_bfloat16* __restrict__ Yh, __nv_bfloat16* __restrict__ Yl,
                float* __restrict__ Yf,
                float* __restrict__ sumP, float* __restrict__ sqP)
{
    constexpr int NCH = KTOT / 64;
    constexpr int PSZ = 128 * 128;     // bytes per plane (128 rows x 128B)

    extern __shared__ char smem[];
    __shared__ int s_src[128], s_dst[128];
    __shared__ float s_sum[128], s_sq[128];

    const uint32_t sbase = smem_to_u32(smem);
    const uint32_t sAh = sbase, sAl = sbase + PSZ, sBh = sbase + 2*PSZ, sBl = sbase + 3*PSZ;

    int tid = threadIdx.x, lane = tid & 31, warp = tid >> 5;
    int wm = warp >> 1, wn = warp & 1;
    long m0 = (long)blockIdx.y * 128;
    int  n0 = blockIdx.x * 128;

    const __nv_bfloat16* Bh_ = Bh + (long)n0 * KTOT;
    const __nv_bfloat16* Bl_ = Bl + (long)n0 * KTOT;

    if (tid < 128) { s_sum[tid] = 0.f; s_sq[tid] = 0.f; }
    if (GATHER) {
        if (tid < 128) s_src[tid] = srcv[m0 + tid];
        else           s_dst[tid - 128] = dstv[m0 + (tid - 128)];
    }
    __syncthreads();

    int rowA = tid >> 1, hfA = tid & 1;
    int rowB = tid >> 1, hfB = tid & 1;

    float4 pa[8];
    uint4  pah[4], pal[4];
    uint4  pbh[4], pbl[4];

    auto load_chunk = [&](int c) {
        if (GATHER) {
            const float* p;
            if (c < 4) {
                int node = (c < 2) ? s_src[rowA] : s_dst[rowA];
                p = hsrc + (long)node * D_H + (c & 1) * 64 + hfA * 32;
            } else {
                p = esrc + (m0 + rowA) * D_E + hfA * 32;
            }
            #pragma unroll
            for (int i = 0; i < 8; i++) pa[i] = *(const float4*)(p + i * 4);
        } else {
            const uint4* ph = (const uint4*)(Ah + (m0 + rowA) * KTOT + c * 64 + hfA * 32);
            const uint4* pl = (const uint4*)(Al + (m0 + rowA) * KTOT + c * 64 + hfA * 32);
            #pragma unroll
            for (int j = 0; j < 4; j++) { pah[j] = ph[j]; pal[j] = pl[j]; }
        }
        const uint4* qh = (const uint4*)(Bh_ + (long)rowB * KTOT + c * 64 + hfB * 32);
        const uint4* ql = (const uint4*)(Bl_ + (long)rowB * KTOT + c * 64 + hfB * 32);
        #pragma unroll
        for (int j = 0; j < 4; j++) { pbh[j] = qh[j]; pbl[j] = ql[j]; }
    };

    auto store_chunk = [&]() {
        if (GATHER) {
            #pragma unroll
            for (int i = 0; i < 8; i++) {
                uint32_t off = SWZ((uint32_t)(rowA * 128 + hfA * 64 + i * 8));
                uint2 uh, ul;
                split_pair(pa[i].x, pa[i].y, uh.x, ul.x);
                split_pair(pa[i].z, pa[i].w, uh.y, ul.y);
                *(uint2*)(smem + off)       = uh;
                *(uint2*)(smem + PSZ + off) = ul;
            }
        } else {
            #pragma unroll
            for (int j = 0; j < 4; j++) {
                uint32_t off = SWZ((uint32_t)(rowA * 128 + hfA * 64 + j * 16));
                *(uint4*)(smem + off)       = pah[j];
                *(uint4*)(smem + PSZ + off) = pal[j];
            }
        }
        #pragma unroll
        for (int j = 0; j < 4; j++) {
            uint32_t off = SWZ((uint32_t)(rowB * 128 + hfB * 64 + j * 16));
            *(uint4*)(smem + 2*PSZ + off) = pbh[j];
            *(uint4*)(smem + 3*PSZ + off) = pbl[j];
        }
    };

    float acc[2][8][4];
    #pragma unroll
    for (int i = 0; i < 2; i++)
        #pragma unroll
        for (int j = 0; j < 8; j++)
            #pragma unroll
            for (int q = 0; q < 4; q++) acc[i][j][q] = 0.f;

    load_chunk(0);
    store_chunk();
    __syncthreads();

    for (int c = 0; c < NCH; c++) {
        if (c + 1 < NCH) load_chunk(c + 1);

        #pragma unroll
        for (int kk = 0; kk < 4; kk++) {
            uint32_t ah[2][4], al[2][4], bh[4][4], bl[4][4];
            uint32_t colb = (uint32_t)(kk * 32 + ((lane >> 4) << 4));
            int rA = wm * 32 + (lane & 15);
            #pragma unroll
            for (int mt = 0; mt < 2; mt++) {
                uint32_t off = SWZ((uint32_t)((rA + mt * 16) * 128) + colb);
                ldsm4(ah[mt], sAh + off);
                ldsm4(al[mt], sAl + off);
            }
            int rB = wn * 64 + (lane & 15);
            #pragma unroll
            for (int q = 0; q < 4; q++) {
                uint32_t off = SWZ((uint32_t)((rB + q * 16) * 128) + colb);
                ldsm4(bh[q], sBh + off);
                ldsm4(bl[q], sBl + off);
            }
            #pragma unroll
            for (int mt = 0; mt < 2; mt++)
                #pragma unroll
                for (int q = 0; q < 4; q++) {
                    mma_bf16(acc[mt][2*q],   ah[mt], bh[q][0], bh[q][2]);
                    mma_bf16(acc[mt][2*q+1], ah[mt], bh[q][1], bh[q][3]);
                }
            #pragma unroll
            for (int mt = 0; mt < 2; mt++)
                #pragma unroll
                for (int q = 0; q < 4; q++) {
                    mma_bf16(acc[mt][2*q],   ah[mt], bl[q][0], bl[q][2]);
                    mma_bf16(acc[mt][2*q+1], ah[mt], bl[q][1], bl[q][3]);
                }
            #pragma unroll
            for (int mt = 0; mt < 2; mt++)
                #pragma unroll
                for (int q = 0; q < 4; q++) {
                    mma_bf16(acc[mt][2*q],   al[mt], bh[q][0], bh[q][2]);
                    mma_bf16(acc[mt][2*q+1], al[mt], bh[q][1], bh[q][3]);
                }
        }

        if (c + 1 < NCH) {
            __syncthreads();
            store_chunk();
            __syncthreads();
        }
    }

    // ===== epilogue =====
    int lane4 = lane >> 2, lanem = lane & 3;

    // 1) f = relu(acc + bias) in place
    #pragma unroll
    for (int nt = 0; nt < 8; nt++) {
        int col = wn * 64 + nt * 8 + lanem * 2;
        float b0v = __ldg(&bias[n0 + col]), b1v = __ldg(&bias[n0 + col + 1]);
        #pragma unroll
        for (int mt = 0; mt < 2; mt++) {
            acc[mt][nt][0] = fmaxf(acc[mt][nt][0] + b0v, 0.f);
            acc[mt][nt][1] = fmaxf(acc[mt][nt][1] + b1v, 0.f);
            acc[mt][nt][2] = fmaxf(acc[mt][nt][2] + b0v, 0.f);
            acc[mt][nt][3] = fmaxf(acc[mt][nt][3] + b1v, 0.f);
        }
    }

    // 2) fused column stats: per-thread partials -> shfl over lane4 -> smem -> global
    {
        float ps[16], pq[16];
        #pragma unroll
        for (int nt = 0; nt < 8; nt++) {
            float s0 = acc[0][nt][0] + acc[0][nt][2] + acc[1][nt][0] + acc[1][nt][2];
            float s1 = acc[0][nt][1] + acc[0][nt][3] + acc[1][nt][1] + acc[1][nt][3];
            float q0 = acc[0][nt][0]*acc[0][nt][0] + acc[0][nt][2]*acc[0][nt][2]
                     + acc[1][nt][0]*acc[1][nt][0] + acc[1][nt][2]*acc[1][nt][2];
            float q1 = acc[0][nt][1]*acc[0][nt][1] + acc[0][nt][3]*acc[0][nt][3]
                     + acc[1][nt][1]*acc[1][nt][1] + acc[1][nt][3]*acc[1][nt][3];
            ps[2*nt] = s0; ps[2*nt+1] = s1; pq[2*nt] = q0; pq[2*nt+1] = q1;
        }
        #pragma unroll
        for (int j = 0; j < 16; j++) {
            #pragma unroll
            for (int o = 4; o < 32; o <<= 1) {
                ps[j] += __shfl_xor_sync(0xffffffffu, ps[j], o);
                pq[j] += __shfl_xor_sync(0xffffffffu, pq[j], o);
            }
        }
        if (lane4 == 0) {
            #pragma unroll
            for (int j = 0; j < 16; j++) {
                int col = wn * 64 + (j >> 1) * 8 + lanem * 2 + (j & 1);
                atomicAdd(&s_sum[col], ps[j]);
                atomicAdd(&s_sq[col],  pq[j]);
            }
        }
    }

    __syncthreads();   // stats done by all warps; stage buffers free for reuse

    // 3) stage output tile in smem, then coalesced global stores
    if (OUTPAIR) {
        constexpr int RS = 68;   // u32 row stride (272B, 16B aligned, conflict-free)
        uint32_t* st = (uint32_t*)smem;
        #pragma unroll
        for (int mt = 0; mt < 2; mt++) {
            int r0l = wm * 32 + mt * 16 + lane4;
            #pragma unroll
            for (int nt = 0; nt < 8; nt++) {
                int cp = wn * 32 + nt * 4 + lanem;
                uint32_t hi, lo;
                split_pair(acc[mt][nt][0], acc[mt][nt][1], hi, lo);
                st[r0l * RS + cp] = hi;
                st[128 * RS + r0l * RS + cp] = lo;
                split_pair(acc[mt][nt][2], acc[mt][nt][3], hi, lo);
                st[(r0l + 8) * RS + cp] = hi;
                st[128 * RS + (r0l + 8) * RS + cp] = lo;
            }
        }
        __syncthreads();
        int l16 = tid & 15, rq = tid >> 4;       // 16 rows per iter
        uint32_t* dsts[2] = { (uint32_t*)Yh, (uint32_t*)Yl };
        #pragma unroll
        for (int p = 0; p < 2; p++) {
            #pragma unroll
            for (int it = 0; it < 8; it++) {
                int rowi = it * 16 + rq;
                uint4 v = *(uint4*)&st[p * 128 * RS + rowi * RS + l16 * 4];
                *(uint4*)&dsts[p][(m0 + rowi) * (NTOT / 2) + (n0 >> 1) + l16 * 4] = v;
            }
        }
    } else {
        constexpr int RS = 132;  // f32 row stride (528B, 16B aligned)
        float* st = (float*)smem;
        #pragma unroll
        for (int mt = 0; mt < 2; mt++) {
            int r0l = wm * 32 + mt * 16 + lane4;
            #pragma unroll
            for (int nt = 0; nt < 8; nt++) {
                int col = wn * 64 + nt * 8 + lanem * 2;
                st[r0l * RS + col]           = acc[mt][nt][0];
                st[r0l * RS + col + 1]       = acc[mt][nt][1];
                st[(r0l + 8) * RS + col]     = acc[mt][nt][2];
                st[(r0l + 8) * RS + col + 1] = acc[mt][nt][3];
            }
        }
        __syncthreads();
        int l32 = tid & 31, rq = tid >> 5;       // 8 rows per iter, full 512B rows
        #pragma unroll
        for (int it = 0; it < 16; it++) {
            int rowi = it * 8 + rq;
            float4 v = *(float4*)&st[rowi * RS + l32 * 4];
            *(float4*)&Yf[(m0 + rowi) * NTOT + l32 * 4] = v;
        }
    }

    // 4) global stat atomics (one per column per CTA)
    if (tid < 128) {
        atomicAdd(&sumP[n0 + tid], s_sum[tid]);
        atomicAdd(&sqP[n0 + tid],  s_sq[tid]);
    }
}

// ======================= host launch sequence =====================================
extern "C" void kernel_launch(void* const* d_in, const int* in_sizes, int n_in,
                              void* d_out, int out_size) {
    const float* h     = (const float*)d_in[0];
    const float* e     = (const float*)d_in[1];
    const int*   src   = (const int*)  d_in[2];
    const int*   dst   = (const int*)  d_in[3];
    const float* bn0_g = (const float*)d_in[4];
    const float* bn0_b = (const float*)d_in[5];
    const float* W1    = (const float*)d_in[6];
    const float* b1    = (const float*)d_in[7];
    const float* bn1_g = (const float*)d_in[8];
    const float* bn1_b = (const float*)d_in[9];
    const float* W2    = (const float*)d_in[10];
    const float* b2    = (const float*)d_in[11];
    const float* bn2_g = (const float*)d_in[12];
    const float* bn2_b = (const float*)d_in[13];
    const float* W3    = (const float*)d_in[14];
    const float* b3    = (const float*)d_in[15];
    float* out = (float*)d_out;

    int n_nodes = in_sizes[0] / D_H;
    int n_edges = in_sizes[2];
    float invM = 1.0f / (float)n_edges;
    int ntiles = n_edges / 128;

    __nv_bfloat16 *y1h, *y1l, *w1h, *w1l, *w2h, *w2l;
    float *y2f;
    float *sum0, *sq0, *sum1, *sq1, *sum2, *sq2;
    float *scale0, *shift0, *scale1, *shift1, *scale2, *shift2, *b1f, *b2f;
    cudaGetSymbolAddress((void**)&y1h, g_y1h);
    cudaGetSymbolAddress((void**)&y1l, g_y1l);
    cudaGetSymbolAddress((void**)&y2f, g_y2f);
    cudaGetSymbolAddress((void**)&w1h, g_W1h);
    cudaGetSymbolAddress((void**)&w1l, g_W1l);
    cudaGetSymbolAddress((void**)&w2h, g_W2h);
    cudaGetSymbolAddress((void**)&w2l, g_W2l);
    cudaGetSymbolAddress((void**)&sum0, g_sum0);
    cudaGetSymbolAddress((void**)&sq0,  g_sq0);
    cudaGetSymbolAddress((void**)&sum1, g_sum1);
    cudaGetSymbolAddress((void**)&sq1,  g_sq1);
    cudaGetSymbolAddress((void**)&sum2, g_sum2);
    cudaGetSymbolAddress((void**)&sq2,  g_sq2);
    cudaGetSymbolAddress((void**)&scale0, g_scale0);
    cudaGetSymbolAddress((void**)&shift0, g_shift0);
    cudaGetSymbolAddress((void**)&scale1, g_scale1);
    cudaGetSymbolAddress((void**)&shift1, g_shift1);
    cudaGetSymbolAddress((void**)&scale2, g_scale2);
    cudaGetSymbolAddress((void**)&shift2, g_shift2);
    cudaGetSymbolAddress((void**)&b1f, g_b1f);
    cudaGetSymbolAddress((void**)&b2f, g_b2f);

    // mainloop needs 64KB; epilogue stage: pair 2*128*68*4=69632, f32 128*132*4=67584
    constexpr int SMEM1 = 69632;
    constexpr int SMEM2 = 67584;
    cudaFuncSetAttribute((const void*)gemm_mma_kernel<true, 320, 256, true>,
                         cudaFuncAttributeMaxDynamicSharedMemorySize, SMEM1);
    cudaFuncSetAttribute((const void*)gemm_mma_kernel<false, 256, 128, false>,
                         cudaFuncAttributeMaxDynamicSharedMemorySize, SMEM2);

    // 1) BN0 stats via degree histogram + node-weighted reduce + e column reduce
    zero_kernel<<<(n_nodes + 255) / 256, 256>>>(n_nodes);
    count_kernel<<<(n_edges + 255) / 256, 256>>>(src, dst, n_edges);
    hstats_kernel<<<(n_nodes + NPB - 1) / NPB, 128>>>(h, n_nodes);
    estats_kernel<<<2048, 256>>>(e, n_edges);
    affine_kernel<<<(F0 + 127) / 128, 128>>>(sum0, sq0, bn0_g, bn0_b, scale0, shift0, F0, invM);

    // 2) fold BN0 into W1 (bf16 hi/lo planes) + bias
    foldW_kernel<<<(H1 * F0 + 255) / 256, 256>>>(W1, scale0, w1h, w1l, H1, F0);
    foldB_kernel<<<H1, 128>>>(W1, b1, shift0, b1f, F0);

    // 3) GEMM1: y1 = relu(gather(x) @ W1f^T + b1f); col-stats fused into epilogue.
    //    grid (N,M): sibling N-blocks of one M-tile run adjacently -> e/h L2 reuse.
    gemm_mma_kernel<true, 320, 256, true><<<dim3(2, ntiles), 256, SMEM1>>>(
        h, e, src, dst, nullptr, nullptr, w1h, w1l, b1f, y1h, y1l, nullptr, sum1, sq1);

    // 4) BN1 affine + fold into W2 (stats already accumulated by GEMM1)
    affine_kernel<<<(H1 + 127) / 128, 128>>>(sum1, sq1, bn1_g, bn1_b, scale1, shift1, H1, invM);
    foldW_kernel<<<(H2 * H1 + 255) / 256, 256>>>(W2, scale1, w2h, w2l, H2, H1);
    foldB_kernel<<<H2, 128>>>(W2, b2, shift1, b2f, H1);

    // 5) GEMM2: y2 = relu(y1 @ W2f^T + b2f), fp32 out; col-stats fused.
    gemm_mma_kernel<false, 256, 128, false><<<dim3(1, ntiles), 256, SMEM2>>>(
        nullptr, nullptr, nullptr, nullptr, y1h, y1l, w2h, w2l, b2f,
        nullptr, nullptr, y2f, sum2, sq2);

    // 6) BN2 affine + fold into W3, final matvec
    affine_kernel<<<1, 128>>>(sum2, sq2, bn2_g, bn2_b, scale2, shift2, H2, invM);
    fold3_kernel<<<1, 128>>>(W3, b3);
    out_kernel<<<(n_edges + 7) / 8, 256>>>(y2f, out, n_edges);
}

// round 9
// speedup vs baseline: 2.1112x; 1.1987x over previous
#include <cuda_runtime.h>
#include <cuda_fp16.h>
#include <cstdint>
#include <math.h>

#define D_H   128
#define D_E   64
#define F0    320
#define H1    256
#define H2    128
#define MAX_NODES 50000
#define MAX_EDGES 800000

// ======================= helpers ==================================================
__device__ __forceinline__ uint32_t smem_to_u32(const void* p) {
    uint32_t a;
    asm("{ .reg .u64 t; cvta.to.shared.u64 t, %1; cvt.u32.u64 %0, t; }" : "=r"(a) : "l"(p));
    return a;
}
#define SWZ(off) ((off) ^ (((off) >> 3) & 0x70))

__device__ __forceinline__ void ldsm4(uint32_t* r, uint32_t addr) {
    asm volatile("ldmatrix.sync.aligned.m8n8.x4.shared.b16 {%0,%1,%2,%3}, [%4];"
                 : "=r"(r[0]), "=r"(r[1]), "=r"(r[2]), "=r"(r[3]) : "r"(addr));
}
__device__ __forceinline__ void mma_f16(float* d, const uint32_t* a, uint32_t b0, uint32_t b1) {
    asm volatile("mma.sync.aligned.m16n8k16.row.col.f32.f16.f16.f32 "
                 "{%0,%1,%2,%3}, {%4,%5,%6,%7}, {%8,%9}, {%0,%1,%2,%3};"
                 : "+f"(d[0]), "+f"(d[1]), "+f"(d[2]), "+f"(d[3])
                 : "r"(a[0]), "r"(a[1]), "r"(a[2]), "r"(a[3]), "r"(b0), "r"(b1));
}
// fp16 pair split: (x,y) -> hi half2 + lo half2 (residuals); x ≈ hi.x + lo.x to ~2^-22
__device__ __forceinline__ void split_pair_h(float x, float y, uint32_t& hi, uint32_t& lo) {
    __half2 h = __floats2half2_rn(x, y);
    float2 hf = __half22float2(h);
    __half2 l = __floats2half2_rn(x - hf.x, y - hf.y);
    hi = *reinterpret_cast<uint32_t*>(&h);
    lo = *reinterpret_cast<uint32_t*>(&l);
}

// ======================= device scratch ==========================================
__device__ __half g_y1h[(size_t)MAX_EDGES * H1];
__device__ __half g_y1l[(size_t)MAX_EDGES * H1];
__device__ float  g_y2f[(size_t)MAX_EDGES * H2];
__device__ __half g_W1h[H1 * F0];
__device__ __half g_W2h[H2 * H1];
__device__ int   g_cnt_src[MAX_NODES];
__device__ int   g_cnt_dst[MAX_NODES];
__device__ float g_sum0[F0], g_sq0[F0];
__device__ float g_sum1[H1], g_sq1[H1];
__device__ float g_sum2[H2], g_sq2[H2];
__device__ float g_scale0[F0], g_shift0[F0];
__device__ float g_scale1[H1], g_shift1[H1];
__device__ float g_scale2[H2], g_shift2[H2];
__device__ float g_b1f[H1], g_b2f[H2];
__device__ float g_W3f[H2];
__device__ float g_b3f[1];

// ======================= setup / stats kernels ===================================
__global__ void zero_kernel(int n_nodes) {
    int i = blockIdx.x * blockDim.x + threadIdx.x;
    if (i < n_nodes) { g_cnt_src[i] = 0; g_cnt_dst[i] = 0; }
    if (i < F0) { g_sum0[i] = 0.f; g_sq0[i] = 0.f; }
    if (i < H1) { g_sum1[i] = 0.f; g_sq1[i] = 0.f; }
    if (i < H2) { g_sum2[i] = 0.f; g_sq2[i] = 0.f; }
}

__global__ void count_kernel(const int* __restrict__ src, const int* __restrict__ dst, int n) {
    int i = blockIdx.x * blockDim.x + threadIdx.x;
    if (i < n) {
        atomicAdd(&g_cnt_src[src[i]], 1);
        atomicAdd(&g_cnt_dst[dst[i]], 1);
    }
}

#define NPB 256
__global__ void hstats_kernel(const float* __restrict__ h, int n_nodes) {
    __shared__ float c1s[NPB], c2s[NPB];
    int t  = threadIdx.x;
    int v0 = blockIdx.x * NPB;
    for (int i = t; i < NPB; i += 128) {
        int v = v0 + i;
        c1s[i] = (v < n_nodes) ? (float)g_cnt_src[v] : 0.f;
        c2s[i] = (v < n_nodes) ? (float)g_cnt_dst[v] : 0.f;
    }
    __syncthreads();
    float s1 = 0.f, q1 = 0.f, s2 = 0.f, q2 = 0.f;
    int lim = n_nodes - v0; if (lim > NPB) lim = NPB;
    for (int i = 0; i < lim; i++) {
        float x  = h[(long)(v0 + i) * D_H + t];
        float x2 = x * x;
        s1 += c1s[i] * x; q1 += c1s[i] * x2;
        s2 += c2s[i] * x; q2 += c2s[i] * x2;
    }
    atomicAdd(&g_sum0[t], s1);          atomicAdd(&g_sq0[t], q1);
    atomicAdd(&g_sum0[D_H + t], s2);    atomicAdd(&g_sq0[D_H + t], q2);
}

// e column stats: 4 independent load streams for MLP, block smem reduce, few atomics.
__global__ void estats_kernel(const float* __restrict__ e, int M) {
    __shared__ float ss[4][64], sq_[4][64];
    int t = threadIdx.x & 63, r = threadIdx.x >> 6;
    long stride = (long)gridDim.x * 4;
    long row = (long)blockIdx.x * 4 + r;
    float sA = 0, qA = 0, sB = 0, qB = 0;
    long rlim = (long)M - 3 * stride;
    for (; row < rlim; row += 4 * stride) {
        float x0 = e[row * D_E + t];
        float x1 = e[(row + stride) * D_E + t];
        float x2 = e[(row + 2 * stride) * D_E + t];
        float x3 = e[(row + 3 * stride) * D_E + t];
        sA += x0 + x1; qA += x0 * x0 + x1 * x1;
        sB += x2 + x3; qB += x2 * x2 + x3 * x3;
    }
    for (; row < M; row += stride) { float x = e[row * D_E + t]; sA += x; qA += x * x; }
    ss[r][t] = sA + sB; sq_[r][t] = qA + qB;
    __syncthreads();
    if (threadIdx.x < 64) {
        float S = ss[0][t] + ss[1][t] + ss[2][t] + ss[3][t];
        float Q = sq_[0][t] + sq_[1][t] + sq_[2][t] + sq_[3][t];
        atomicAdd(&g_sum0[2 * D_H + t], S);
        atomicAdd(&g_sq0 [2 * D_H + t], Q);
    }
}

__global__ void affine_kernel(const float* __restrict__ sum, const float* __restrict__ sq,
                              const float* __restrict__ g, const float* __restrict__ b,
                              float* __restrict__ scale, float* __restrict__ shift,
                              int K, float invM) {
    int j = blockIdx.x * blockDim.x + threadIdx.x;
    if (j < K) {
        float mean = sum[j] * invM;
        float var  = sq[j] * invM - mean * mean;
        float sc   = g[j] * rsqrtf(var + 1e-5f);
        scale[j] = sc;
        shift[j] = b[j] - mean * sc;
    }
}

// Wh[n][k] = fp16( W[n][k] * scale[k] )
__global__ void foldW_kernel(const float* __restrict__ W, const float* __restrict__ scale,
                             __half* __restrict__ Wh, int N, int K) {
    int idx = blockIdx.x * blockDim.x + threadIdx.x;
    if (idx < N * K) {
        int k = idx % K;
        Wh[idx] = __float2half(W[idx] * scale[k]);
    }
}

__global__ void foldB_kernel(const float* __restrict__ W, const float* __restrict__ bvec,
                             const float* __restrict__ shift, float* __restrict__ bout, int K) {
    int o = blockIdx.x, t = threadIdx.x;
    float s = 0.f;
    for (int j = t; j < K; j += 128) s += W[(long)o * K + j] * shift[j];
    __shared__ float red[128];
    red[t] = s; __syncthreads();
    for (int w = 64; w > 0; w >>= 1) { if (t < w) red[t] += red[t + w]; __syncthreads(); }
    if (t == 0) bout[o] = bvec[o] + red[0];
}

__global__ void fold3_kernel(const float* __restrict__ W3, const float* __restrict__ b3) {
    int t = threadIdx.x;
    float w = W3[t];
    g_W3f[t] = w * g_scale2[t];
    __shared__ float red[128];
    red[t] = w * g_shift2[t]; __syncthreads();
    for (int w2 = 64; w2 > 0; w2 >>= 1) { if (t < w2) red[t] += red[t + w2]; __syncthreads(); }
    if (t == 0) g_b3f[0] = b3[0] + red[0];
}

__global__ void out_kernel(const float* __restrict__ Y2, float* __restrict__ out, int M) {
    int warp = (blockIdx.x * blockDim.x + threadIdx.x) >> 5;
    int lane = threadIdx.x & 31;
    if (warp >= M) return;
    float4 v = ((const float4*)(Y2 + (long)warp * H2))[lane];
    int c = lane * 4;
    float s = v.x * g_W3f[c] + v.y * g_W3f[c + 1] + v.z * g_W3f[c + 2] + v.w * g_W3f[c + 3];
    #pragma unroll
    for (int o = 16; o > 0; o >>= 1) s += __shfl_down_sync(0xffffffffu, s, o);
    if (lane == 0) out[warp] = s + g_b3f[0];
}

// ======================= mma.sync fp16x2 GEMM =====================================
// Y[m][n] = relu( sum_k A[m][k]*B[n][k] + bias[n] )
// A as fp16 hi+lo planes (exact to ~2^-22), B single fp16 plane.
// 2 tensor products (hi*B + lo*B) with fp32 accumulation.
// CTA tile M=128, N=128; K staged in 64-element chunks; grid = (N-blocks, M-tiles).
// Epilogue: fused column sum/sumsq + smem-staged coalesced stores.
// OUTPAIR: fp16 hi/lo planes out; else fp32 plane out.

template<bool GATHER, int KTOT, int NTOT, bool OUTPAIR>
__global__ void __launch_bounds__(256, 1)
gemm_mma_kernel(const float* __restrict__ hsrc, const float* __restrict__ esrc,
                const int* __restrict__ srcv, const int* __restrict__ dstv,
                const __half* __restrict__ Ah, const __half* __restrict__ Al,
                const __half* __restrict__ Bh,
                const float* __restrict__ bias,
                __half* __restrict__ Yh, __half* __restrict__ Yl,
                float* __restrict__ Yf,
                float* __restrict__ sumP, float* __restrict__ sqP)
{
    constexpr int NCH = KTOT / 64;
    constexpr int PSZ = 128 * 128;     // bytes per plane (128 rows x 128B)

    extern __shared__ char smem[];
    __shared__ int s_src[128], s_dst[128];
    __shared__ float s_sum[128], s_sq[128];

    const uint32_t sbase = smem_to_u32(smem);
    const uint32_t sAh = sbase, sAl = sbase + PSZ, sBh = sbase + 2*PSZ;

    int tid = threadIdx.x, lane = tid & 31, warp = tid >> 5;
    int wm = warp >> 1, wn = warp & 1;
    long m0 = (long)blockIdx.y * 128;
    int  n0 = blockIdx.x * 128;

    const __half* Bh_ = Bh + (long)n0 * KTOT;

    if (tid < 128) { s_sum[tid] = 0.f; s_sq[tid] = 0.f; }
    if (GATHER) {
        if (tid < 128) s_src[tid] = srcv[m0 + tid];
        else           s_dst[tid - 128] = dstv[m0 + (tid - 128)];
    }
    __syncthreads();

    int rowA = tid >> 1, hfA = tid & 1;
    int rowB = tid >> 1, hfB = tid & 1;

    float4 pa[8];
    uint4  pah[4], pal[4];
    uint4  pbh[4];

    auto load_chunk = [&](int c) {
        if (GATHER) {
            const float* p;
            if (c < 4) {
                int node = (c < 2) ? s_src[rowA] : s_dst[rowA];
                p = hsrc + (long)node * D_H + (c & 1) * 64 + hfA * 32;
            } else {
                p = esrc + (m0 + rowA) * D_E + hfA * 32;
            }
            #pragma unroll
            for (int i = 0; i < 8; i++) pa[i] = *(const float4*)(p + i * 4);
        } else {
            const uint4* ph = (const uint4*)(Ah + (m0 + rowA) * KTOT + c * 64 + hfA * 32);
            const uint4* pl = (const uint4*)(Al + (m0 + rowA) * KTOT + c * 64 + hfA * 32);
            #pragma unroll
            for (int j = 0; j < 4; j++) { pah[j] = ph[j]; pal[j] = pl[j]; }
        }
        const uint4* qh = (const uint4*)(Bh_ + (long)rowB * KTOT + c * 64 + hfB * 32);
        #pragma unroll
        for (int j = 0; j < 4; j++) { pbh[j] = qh[j]; }
    };

    auto store_chunk = [&]() {
        if (GATHER) {
            #pragma unroll
            for (int i = 0; i < 8; i++) {
                uint32_t off = SWZ((uint32_t)(rowA * 128 + hfA * 64 + i * 8));
                uint2 uh, ul;
                split_pair_h(pa[i].x, pa[i].y, uh.x, ul.x);
                split_pair_h(pa[i].z, pa[i].w, uh.y, ul.y);
                *(uint2*)(smem + off)       = uh;
                *(uint2*)(smem + PSZ + off) = ul;
            }
        } else {
            #pragma unroll
            for (int j = 0; j < 4; j++) {
                uint32_t off = SWZ((uint32_t)(rowA * 128 + hfA * 64 + j * 16));
                *(uint4*)(smem + off)       = pah[j];
                *(uint4*)(smem + PSZ + off) = pal[j];
            }
        }
        #pragma unroll
        for (int j = 0; j < 4; j++) {
            uint32_t off = SWZ((uint32_t)(rowB * 128 + hfB * 64 + j * 16));
            *(uint4*)(smem + 2*PSZ + off) = pbh[j];
        }
    };

    float acc[2][8][4];
    #pragma unroll
    for (int i = 0; i < 2; i++)
        #pragma unroll
        for (int j = 0; j < 8; j++)
            #pragma unroll
            for (int q = 0; q < 4; q++) acc[i][j][q] = 0.f;

    load_chunk(0);
    store_chunk();
    __syncthreads();

    for (int c = 0; c < NCH; c++) {
        if (c + 1 < NCH) load_chunk(c + 1);

        #pragma unroll
        for (int kk = 0; kk < 4; kk++) {
            uint32_t ah[2][4], al[2][4], bh[4][4];
            uint32_t colb = (uint32_t)(kk * 32 + ((lane >> 4) << 4));
            int rA = wm * 32 + (lane & 15);
            #pragma unroll
            for (int mt = 0; mt < 2; mt++) {
                uint32_t off = SWZ((uint32_t)((rA + mt * 16) * 128) + colb);
                ldsm4(ah[mt], sAh + off);
                ldsm4(al[mt], sAl + off);
            }
            int rB = wn * 64 + (lane & 15);
            #pragma unroll
            for (int q = 0; q < 4; q++) {
                uint32_t off = SWZ((uint32_t)((rB + q * 16) * 128) + colb);
                ldsm4(bh[q], sBh + off);
            }
            // hi * B
            #pragma unroll
            for (int mt = 0; mt < 2; mt++)
                #pragma unroll
                for (int q = 0; q < 4; q++) {
                    mma_f16(acc[mt][2*q],   ah[mt], bh[q][0], bh[q][2]);
                    mma_f16(acc[mt][2*q+1], ah[mt], bh[q][1], bh[q][3]);
                }
            // lo * B
            #pragma unroll
            for (int mt = 0; mt < 2; mt++)
                #pragma unroll
                for (int q = 0; q < 4; q++) {
                    mma_f16(acc[mt][2*q],   al[mt], bh[q][0], bh[q][2]);
                    mma_f16(acc[mt][2*q+1], al[mt], bh[q][1], bh[q][3]);
                }
        }

        if (c + 1 < NCH) {
            __syncthreads();
            store_chunk();
            __syncthreads();
        }
    }

    // ===== epilogue =====
    int lane4 = lane >> 2, lanem = lane & 3;

    // 1) f = relu(acc + bias) in place
    #pragma unroll
    for (int nt = 0; nt < 8; nt++) {
        int col = wn * 64 + nt * 8 + lanem * 2;
        float b0v = __ldg(&bias[n0 + col]), b1v = __ldg(&bias[n0 + col + 1]);
        #pragma unroll
        for (int mt = 0; mt < 2; mt++) {
            acc[mt][nt][0] = fmaxf(acc[mt][nt][0] + b0v, 0.f);
            acc[mt][nt][1] = fmaxf(acc[mt][nt][1] + b1v, 0.f);
            acc[mt][nt][2] = fmaxf(acc[mt][nt][2] + b0v, 0.f);
            acc[mt][nt][3] = fmaxf(acc[mt][nt][3] + b1v, 0.f);
        }
    }

    // 2) fused column stats: per-thread partials -> shfl over lane4 -> smem -> global
    {
        float ps[16], pq[16];
        #pragma unroll
        for (int nt = 0; nt < 8; nt++) {
            float s0 = acc[0][nt][0] + acc[0][nt][2] + acc[1][nt][0] + acc[1][nt][2];
            float s1 = acc[0][nt][1] + acc[0][nt][3] + acc[1][nt][1] + acc[1][nt][3];
            float q0 = acc[0][nt][0]*acc[0][nt][0] + acc[0][nt][2]*acc[0][nt][2]
                     + acc[1][nt][0]*acc[1][nt][0] + acc[1][nt][2]*acc[1][nt][2];
            float q1 = acc[0][nt][1]*acc[0][nt][1] + acc[0][nt][3]*acc[0][nt][3]
                     + acc[1][nt][1]*acc[1][nt][1] + acc[1][nt][3]*acc[1][nt][3];
            ps[2*nt] = s0; ps[2*nt+1] = s1; pq[2*nt] = q0; pq[2*nt+1] = q1;
        }
        #pragma unroll
        for (int j = 0; j < 16; j++) {
            #pragma unroll
            for (int o = 4; o < 32; o <<= 1) {
                ps[j] += __shfl_xor_sync(0xffffffffu, ps[j], o);
                pq[j] += __shfl_xor_sync(0xffffffffu, pq[j], o);
            }
        }
        if (lane4 == 0) {
            #pragma unroll
            for (int j = 0; j < 16; j++) {
                int col = wn * 64 + (j >> 1) * 8 + lanem * 2 + (j & 1);
                atomicAdd(&s_sum[col], ps[j]);
                atomicAdd(&s_sq[col],  pq[j]);
            }
        }
    }

    __syncthreads();   // stats done by all warps; stage buffers free for reuse

    // 3) stage output tile in smem, then coalesced global stores
    if (OUTPAIR) {
        constexpr int RS = 68;   // u32 row stride (272B, 16B aligned)
        uint32_t* st = (uint32_t*)smem;
        #pragma unroll
        for (int mt = 0; mt < 2; mt++) {
            int r0l = wm * 32 + mt * 16 + lane4;
            #pragma unroll
            for (int nt = 0; nt < 8; nt++) {
                int cp = wn * 32 + nt * 4 + lanem;
                uint32_t hi, lo;
                split_pair_h(acc[mt][nt][0], acc[mt][nt][1], hi, lo);
                st[r0l * RS + cp] = hi;
                st[128 * RS + r0l * RS + cp] = lo;
                split_pair_h(acc[mt][nt][2], acc[mt][nt][3], hi, lo);
                st[(r0l + 8) * RS + cp] = hi;
                st[128 * RS + (r0l + 8) * RS + cp] = lo;
            }
        }
        __syncthreads();
        int l16 = tid & 15, rq = tid >> 4;       // 16 rows per iter
        uint32_t* dsts[2] = { (uint32_t*)Yh, (uint32_t*)Yl };
        #pragma unroll
        for (int p = 0; p < 2; p++) {
            #pragma unroll
            for (int it = 0; it < 8; it++) {
                int rowi = it * 16 + rq;
                uint4 v = *(uint4*)&st[p * 128 * RS + rowi * RS + l16 * 4];
                *(uint4*)&dsts[p][(m0 + rowi) * (NTOT / 2) + (n0 >> 1) + l16 * 4] = v;
            }
        }
    } else {
        constexpr int RS = 132;  // f32 row stride (528B, 16B aligned)
        float* st = (float*)smem;
        #pragma unroll
        for (int mt = 0; mt < 2; mt++) {
            int r0l = wm * 32 + mt * 16 + lane4;
            #pragma unroll
            for (int nt = 0; nt < 8; nt++) {
                int col = wn * 64 + nt * 8 + lanem * 2;
                st[r0l * RS + col]           = acc[mt][nt][0];
                st[r0l * RS + col + 1]       = acc[mt][nt][1];
                st[(r0l + 8) * RS + col]     = acc[mt][nt][2];
                st[(r0l + 8) * RS + col + 1] = acc[mt][nt][3];
            }
        }
        __syncthreads();
        int l32 = tid & 31, rq = tid >> 5;       // 8 rows per iter, full 512B rows
        #pragma unroll
        for (int it = 0; it < 16; it++) {
            int rowi = it * 8 + rq;
            float4 v = *(float4*)&st[rowi * RS + l32 * 4];
            *(float4*)&Yf[(m0 + rowi) * NTOT + l32 * 4] = v;
        }
    }

    // 4) global stat atomics (one per column per CTA)
    if (tid < 128) {
        atomicAdd(&sumP[n0 + tid], s_sum[tid]);
        atomicAdd(&sqP[n0 + tid],  s_sq[tid]);
    }
}

// ======================= host launch sequence =====================================
extern "C" void kernel_launch(void* const* d_in, const int* in_sizes, int n_in,
                              void* d_out, int out_size) {
    const float* h     = (const float*)d_in[0];
    const float* e     = (const float*)d_in[1];
    const int*   src   = (const int*)  d_in[2];
    const int*   dst   = (const int*)  d_in[3];
    const float* bn0_g = (const float*)d_in[4];
    const float* bn0_b = (const float*)d_in[5];
    const float* W1    = (const float*)d_in[6];
    const float* b1    = (const float*)d_in[7];
    const float* bn1_g = (const float*)d_in[8];
    const float* bn1_b = (const float*)d_in[9];
    const float* W2    = (const float*)d_in[10];
    const float* b2    = (const float*)d_in[11];
    const float* bn2_g = (const float*)d_in[12];
    const float* bn2_b = (const float*)d_in[13];
    const float* W3    = (const float*)d_in[14];
    const float* b3    = (const float*)d_in[15];
    float* out = (float*)d_out;

    int n_nodes = in_sizes[0] / D_H;
    int n_edges = in_sizes[2];
    float invM = 1.0f / (float)n_edges;
    int ntiles = n_edges / 128;

    __half *y1h, *y1l, *w1h, *w2h;
    float *y2f;
    float *sum0, *sq0, *sum1, *sq1, *sum2, *sq2;
    float *scale0, *shift0, *scale1, *shift1, *scale2, *shift2, *b1f, *b2f;
    cudaGetSymbolAddress((void**)&y1h, g_y1h);
    cudaGetSymbolAddress((void**)&y1l, g_y1l);
    cudaGetSymbolAddress((void**)&y2f, g_y2f);
    cudaGetSymbolAddress((void**)&w1h, g_W1h);
    cudaGetSymbolAddress((void**)&w2h, g_W2h);
    cudaGetSymbolAddress((void**)&sum0, g_sum0);
    cudaGetSymbolAddress((void**)&sq0,  g_sq0);
    cudaGetSymbolAddress((void**)&sum1, g_sum1);
    cudaGetSymbolAddress((void**)&sq1,  g_sq1);
    cudaGetSymbolAddress((void**)&sum2, g_sum2);
    cudaGetSymbolAddress((void**)&sq2,  g_sq2);
    cudaGetSymbolAddress((void**)&scale0, g_scale0);
    cudaGetSymbolAddress((void**)&shift0, g_shift0);
    cudaGetSymbolAddress((void**)&scale1, g_scale1);
    cudaGetSymbolAddress((void**)&shift1, g_shift1);
    cudaGetSymbolAddress((void**)&scale2, g_scale2);
    cudaGetSymbolAddress((void**)&shift2, g_shift2);
    cudaGetSymbolAddress((void**)&b1f, g_b1f);
    cudaGetSymbolAddress((void**)&b2f, g_b2f);

    // mainloop: 3 planes * 16KB = 49152; epilogue stage: pair 69632, f32 67584
    constexpr int SMEM1 = 69632;
    constexpr int SMEM2 = 67584;
    cudaFuncSetAttribute((const void*)gemm_mma_kernel<true, 320, 256, true>,
                         cudaFuncAttributeMaxDynamicSharedMemorySize, SMEM1);
    cudaFuncSetAttribute((const void*)gemm_mma_kernel<false, 256, 128, false>,
                         cudaFuncAttributeMaxDynamicSharedMemorySize, SMEM2);

    // 1) BN0 stats via degree histogram + node-weighted reduce + e column reduce
    zero_kernel<<<(n_nodes + 255) / 256, 256>>>(n_nodes);
    count_kernel<<<(n_edges + 255) / 256, 256>>>(src, dst, n_edges);
    hstats_kernel<<<(n_nodes + NPB - 1) / NPB, 128>>>(h, n_nodes);
    estats_kernel<<<2048, 256>>>(e, n_edges);
    affine_kernel<<<(F0 + 127) / 128, 128>>>(sum0, sq0, bn0_g, bn0_b, scale0, shift0, F0, invM);

    // 2) fold BN0 into W1 (single fp16 plane) + bias
    foldW_kernel<<<(H1 * F0 + 255) / 256, 256>>>(W1, scale0, w1h, H1, F0);
    foldB_kernel<<<H1, 128>>>(W1, b1, shift0, b1f, F0);

    // 3) GEMM1: y1 = relu(gather(x) @ W1f^T + b1f); fp16 pair out; stats fused.
    gemm_mma_kernel<true, 320, 256, true><<<dim3(2, ntiles), 256, SMEM1>>>(
        h, e, src, dst, nullptr, nullptr, w1h, b1f, y1h, y1l, nullptr, sum1, sq1);

    // 4) BN1 affine + fold into W2
    affine_kernel<<<(H1 + 127) / 128, 128>>>(sum1, sq1, bn1_g, bn1_b, scale1, shift1, H1, invM);
    foldW_kernel<<<(H2 * H1 + 255) / 256, 256>>>(W2, scale1, w2h, H2, H1);
    foldB_kernel<<<H2, 128>>>(W2, b2, shift1, b2f, H1);

    // 5) GEMM2: y2 = relu(y1 @ W2f^T + b2f), fp32 out; stats fused.
    gemm_mma_kernel<false, 256, 128, false><<<dim3(1, ntiles), 256, SMEM2>>>(
        nullptr, nullptr, nullptr, nullptr, y1h, y1l, w2h, b2f,
        nullptr, nullptr, y2f, sum2, sq2);

    // 6) BN2 affine + fold into W3, final matvec
    affine_kernel<<<1, 128>>>(sum2, sq2, bn2_g, bn2_b, scale2, shift2, H2, invM);
    fold3_kernel<<<1, 128>>>(W3, b3);
    out_kernel<<<(n_edges + 7) / 8, 256>>>(y2f, out, n_edges);
}